// round 1
// baseline (speedup 1.0000x reference)
#include <cuda_runtime.h>
#include <cstdint>

// Packed fp32x2 FMA (Blackwell sm_100+; ptxas never auto-fuses this from C++).
__device__ __forceinline__ unsigned long long fma2(unsigned long long a,
                                                   unsigned long long b,
                                                   unsigned long long c) {
    unsigned long long d;
    asm("fma.rn.f32x2 %0, %1, %2, %3;" : "=l"(d) : "l"(a), "l"(b), "l"(c));
    return d;
}

// b0[r,f,n] = sum_m CG0[r,m]*A[f,m,n]  (r=0..7)
// b1[r,f,n] = sum_m CG1[r,m]*A[f,m,n]  (r=0..23)
// A: [F, M, 1024] fp32; each thread handles one (f, n-pair), fusing both CG
// passes so A is read from HBM exactly once.
template <int M, int F>
__global__ void __launch_bounds__(256, 2)
sym_kernel(const float* __restrict__ A,
           const float* __restrict__ cg0,
           const float* __restrict__ cg1,
           float* __restrict__ out0,
           float* __restrict__ out1) {
    // CG staged in shared as duplicated f32x2 pairs: cgp[mi*32 + r] = (c, c).
    __shared__ __align__(16) unsigned long long cgp[M * 32];
    const int tid = threadIdx.x;
    for (int i = tid; i < M * 32; i += 256) {
        const int mi = i >> 5;
        const int r = i & 31;
        const float c = (r < 8) ? cg0[r * M + mi] : cg1[(r - 8) * M + mi];
        unsigned long long p = (unsigned long long)__float_as_uint(c);
        p |= p << 32;
        cgp[i] = p;
    }
    __syncthreads();

    const int f = blockIdx.x;                       // 0..F-1
    const int n0 = blockIdx.y * 512 + tid * 2;      // 0..1022 (even)

    unsigned long long acc[32];
#pragma unroll
    for (int r = 0; r < 32; r++) acc[r] = 0ull;     // (0.0f, 0.0f)

    const float* aptr = A + (size_t)f * (M * 1024) + n0;

#pragma unroll 4
    for (int mi = 0; mi < M; ++mi) {
        // Coalesced 8B load of A[f, mi, n0:n0+2]
        const unsigned long long a2 =
            *reinterpret_cast<const unsigned long long*>(aptr + (size_t)mi * 1024);
        const unsigned long long* crow = &cgp[mi * 32];
#pragma unroll
        for (int r = 0; r < 32; r += 2) {
            // LDS.128: two duplicated CG values per shared load (broadcast).
            const ulonglong2 c = *reinterpret_cast<const ulonglong2*>(crow + r);
            acc[r]     = fma2(c.x, a2, acc[r]);
            acc[r + 1] = fma2(c.y, a2, acc[r + 1]);
        }
    }

#pragma unroll
    for (int r = 0; r < 8; r++) {
        *reinterpret_cast<unsigned long long*>(
            out0 + ((size_t)r * F + f) * 1024 + n0) = acc[r];
    }
#pragma unroll
    for (int r = 0; r < 24; r++) {
        *reinterpret_cast<unsigned long long*>(
            out1 + ((size_t)r * F + f) * 1024 + n0) = acc[8 + r];
    }
}

extern "C" void kernel_launch(void* const* d_in, const int* in_sizes, int n_in,
                              void* d_out, int out_size) {
    (void)in_sizes; (void)n_in; (void)out_size;
    const float* A2_l11  = (const float*)d_in[0];   // [1024,  9, 1024]
    const float* A2_l22  = (const float*)d_in[1];   // [1024, 25, 1024]
    const float* A2_l33  = (const float*)d_in[2];   // [1024, 49, 1024]
    const float* A3_l111 = (const float*)d_in[3];   // [ 512, 27, 1024]
    const float* A3_l211 = (const float*)d_in[4];   // [ 512, 45, 1024]
    const float* CG0_0 = (const float*)d_in[5];     // [ 8,  9]
    const float* CG0_1 = (const float*)d_in[6];     // [ 8, 25]
    const float* CG0_2 = (const float*)d_in[7];     // [ 8, 49]
    const float* CG0_3 = (const float*)d_in[8];     // [ 8, 27]
    const float* CG0_4 = (const float*)d_in[9];     // [ 8, 45]
    const float* CG1_0 = (const float*)d_in[10];    // [24,  9]
    const float* CG1_1 = (const float*)d_in[11];    // [24, 25]
    const float* CG1_2 = (const float*)d_in[12];    // [24, 49]
    const float* CG1_3 = (const float*)d_in[13];    // [24, 27]
    const float* CG1_4 = (const float*)d_in[14];    // [24, 45]
    float* out = (float*)d_out;

    // Output region offsets (elements), in tuple order b0(5) then b1(5):
    constexpr size_t o0_0 = 0;
    constexpr size_t o0_1 = o0_0 + (size_t)8 * 1024 * 1024;   //  8388608
    constexpr size_t o0_2 = o0_1 + (size_t)8 * 1024 * 1024;   // 16777216
    constexpr size_t o0_3 = o0_2 + (size_t)8 * 1024 * 1024;   // 25165824
    constexpr size_t o0_4 = o0_3 + (size_t)8 * 512 * 1024;    // 29360128
    constexpr size_t o1_0 = o0_4 + (size_t)8 * 512 * 1024;    // 33554432
    constexpr size_t o1_1 = o1_0 + (size_t)24 * 1024 * 1024;  // 58720256
    constexpr size_t o1_2 = o1_1 + (size_t)24 * 1024 * 1024;  // 83886080
    constexpr size_t o1_3 = o1_2 + (size_t)24 * 1024 * 1024;  // 109051904
    constexpr size_t o1_4 = o1_3 + (size_t)24 * 512 * 1024;   // 121634816

    const dim3 blk(256);
    sym_kernel<9, 1024><<<dim3(1024, 2), blk>>>(A2_l11,  CG0_0, CG1_0, out + o0_0, out + o1_0);
    sym_kernel<25, 1024><<<dim3(1024, 2), blk>>>(A2_l22, CG0_1, CG1_1, out + o0_1, out + o1_1);
    sym_kernel<49, 1024><<<dim3(1024, 2), blk>>>(A2_l33, CG0_2, CG1_2, out + o0_2, out + o1_2);
    sym_kernel<27, 512><<<dim3(512, 2), blk>>>(A3_l111, CG0_3, CG1_3, out + o0_3, out + o1_3);
    sym_kernel<45, 512><<<dim3(512, 2), blk>>>(A3_l211, CG0_4, CG1_4, out + o0_4, out + o1_4);
}